// round 15
// baseline (speedup 1.0000x reference)
#include <cuda_runtime.h>
#include <cuda_fp16.h>
#include <math.h>

#define DIM   128
#define NH    4
#define HD    32
#define WS    7
#define SS    3
#define ZP    14
#define HP    56
#define WP    56
#define NTOK  343
#define PADN  352
#define NWIN  256
#define NROWS (NWIN * NTOK)   // 87808
#define NMLP  512
// QK scale folded with 1/ln2 for exp2-based softmax: (1/sqrt(32)) * (1/ln 2)
#define QK_SCALE_LOG2 0.25503164402847864f
#define INV_LN2 1.4426950408889634f

// -------- scratch (static device globals) --------
__device__ __half g_xw [NROWS * DIM];
__device__ __half g_qkv[NROWS * 3 * DIM];
__device__ __half g_att[NROWS * DIM];
__device__ float  g_x1 [NROWS * DIM];
__device__ __half g_xn2[NROWS * DIM];
__device__ __half g_h  [NROWS * NMLP];
__device__ __half g_wh [196608];                       // fp16 weights [K][N]: qkv|proj|fc1|fc2
__device__ __half g_btab[8 * NH * PADN * PADN];        // (bias+mask)/ln2 table (7.9MB)

__device__ __forceinline__ int nat_row(int r) {
    int w = r / NTOK, t = r - w * NTOK;
    int b = w >> 7, wi = w & 127;
    int wz = wi >> 6, wy = (wi >> 3) & 7, wx = wi & 7;
    int lz = t / 49, rem = t - lz * 49, ly = rem / 7, lx = rem - ly * 7;
    int z = wz * WS + lz + SS; if (z >= ZP) z -= ZP;
    int y = wy * WS + ly + SS; if (y >= HP) y -= HP;
    int x = wx * WS + lx + SS; if (x >= WP) x -= WP;
    return ((b * ZP + z) * HP + y) * WP + x;
}

// -------- merged prologue: weight convert + bias/mask table (one launch) --------
#define NBTAB (8 * NH * PADN * PADN)
__global__ void prologue_kernel(const float* __restrict__ qkvw, const float* __restrict__ projw,
                                const float* __restrict__ fc1w, const float* __restrict__ fc2w,
                                __half* __restrict__ o,
                                const float* __restrict__ rel, __half* __restrict__ tab) {
    int idx = blockIdx.x * 256 + threadIdx.x;
    if (idx < 196608) {
        float v;
        if (idx < 49152) v = qkvw[idx];
        else if (idx < 65536) v = projw[idx - 49152];
        else if (idx < 131072) v = fc1w[idx - 65536];
        else v = fc2w[idx - 131072];
        o[idx] = __float2half(v);
    }
    if (idx >= NBTAB) return;
    int j = idx % PADN, t1 = idx / PADN;
    int i = t1 % PADN, t2 = t1 / PADN;
    int h = t2 & 3, wt = t2 >> 2;
    float val;
    if (i >= NTOK || j >= NTOK) val = -30000.f;
    else {
        int iz = i / 49, ir = i - iz * 49, iy = ir / 7, ix = ir - iy * 7;
        int jz = j / 49, jr = j - jz * 49, jy = jr / 7, jx = jr - jy * 7;
        int ridx = (iz - jz + 6) * 169 + (iy - jy + 6) * 13 + (ix - jx + 6);
        int ri = ((wt & 4) ? ((iz < 4) ? 1 : 2) : 0) * 9
               + ((wt & 2) ? ((iy < 4) ? 1 : 2) : 0) * 3
               + ((wt & 1) ? ((ix < 4) ? 1 : 2) : 0);
        int rj = ((wt & 4) ? ((jz < 4) ? 1 : 2) : 0) * 9
               + ((wt & 2) ? ((jy < 4) ? 1 : 2) : 0) * 3
               + ((wt & 1) ? ((jx < 4) ? 1 : 2) : 0);
        val = (rel[ridx * NH + h] + ((ri == rj) ? 0.f : -100.f)) * INV_LN2;
    }
    tab[idx] = __float2half(val);
}

// -------- LayerNorm (LN1): one warp per token, gather + fp16 out, 512 thr --------
__global__ void ln_kernel(const float* __restrict__ src, const float* __restrict__ g,
                          const float* __restrict__ b, __half* __restrict__ dst, int gather) {
    int token = blockIdx.x * 16 + (threadIdx.x >> 5);
    int lane  = threadIdx.x & 31;
    int srow  = gather ? nat_row(token) : token;
    float4 v = ((const float4*)(src + (size_t)srow * DIM))[lane];
    float s  = v.x + v.y + v.z + v.w;
    float ss = v.x * v.x + v.y * v.y + v.z * v.z + v.w * v.w;
#pragma unroll
    for (int o = 16; o; o >>= 1) {
        s  += __shfl_xor_sync(0xffffffffu, s,  o);
        ss += __shfl_xor_sync(0xffffffffu, ss, o);
    }
    float mean = s * (1.f / 128.f);
    float inv  = rsqrtf(ss * (1.f / 128.f) - mean * mean + 1e-5f);
    float4 gg = ((const float4*)g)[lane];
    float4 bb = ((const float4*)b)[lane];
    __half2 h01 = __floats2half2_rn((v.x - mean) * inv * gg.x + bb.x,
                                    (v.y - mean) * inv * gg.y + bb.y);
    __half2 h23 = __floats2half2_rn((v.z - mean) * inv * gg.z + bb.z,
                                    (v.w - mean) * inv * gg.w + bb.w);
    __half2* d = (__half2*)(dst + (size_t)token * DIM);
    d[lane * 2] = h01; d[lane * 2 + 1] = h23;
}

// ================= MMA helpers =================
__device__ __forceinline__ void ldsm_x4(unsigned (&r)[4], unsigned addr) {
    asm volatile("ldmatrix.sync.aligned.m8n8.x4.shared.b16 {%0,%1,%2,%3}, [%4];"
                 : "=r"(r[0]), "=r"(r[1]), "=r"(r[2]), "=r"(r[3]) : "r"(addr));
}
__device__ __forceinline__ void ldsm_x4_t(unsigned (&r)[4], unsigned addr) {
    asm volatile("ldmatrix.sync.aligned.m8n8.x4.trans.shared.b16 {%0,%1,%2,%3}, [%4];"
                 : "=r"(r[0]), "=r"(r[1]), "=r"(r[2]), "=r"(r[3]) : "r"(addr));
}
__device__ __forceinline__ void mma16816(float (&c)[4], const unsigned (&a)[4],
                                         unsigned b0, unsigned b1) {
    asm volatile("mma.sync.aligned.m16n8k16.row.col.f32.f16.f16.f32 "
                 "{%0,%1,%2,%3},{%4,%5,%6,%7},{%8,%9},{%0,%1,%2,%3};"
                 : "+f"(c[0]), "+f"(c[1]), "+f"(c[2]), "+f"(c[3])
                 : "r"(a[0]), "r"(a[1]), "r"(a[2]), "r"(a[3]), "r"(b0), "r"(b1));
}
__device__ __forceinline__ void cpa16(unsigned dst, const void* src) {
    asm volatile("cp.async.cg.shared.global [%0], [%1], 16;" :: "r"(dst), "l"(src));
}
__device__ __forceinline__ void cpa_commit() { asm volatile("cp.async.commit_group;"); }
template <int N> __device__ __forceinline__ void cpa_wait() {
    asm volatile("cp.async.wait_group %0;" :: "n"(N));
}

// ================= tensor-core GEMM, cp.async 4-stage, 1 sync/iter (round-10) ====
#define BK 32
#define STG_A (128 * 40)            // halfs
#define STG_B (BK * 136)
#define STG_TOT (STG_A + STG_B)
#define GEMM_SMEM (4 * STG_TOT * 2) // 75,776 bytes

template <int EPI, typename CT>
__global__ void __launch_bounds__(256, 2) mma_gemm(
        const __half* __restrict__ A, const __half* __restrict__ B,
        const float* __restrict__ bias, const float* __restrict__ res,
        CT* __restrict__ C, const float* __restrict__ g2,
        const float* __restrict__ b2, __half* __restrict__ C2,
        int M, int N, int K) {
    extern __shared__ __half gsm[];
    const int tid  = threadIdx.x;
    const int lane = tid & 31, warp = tid >> 5;
    const int mw = warp >> 2, nw = warp & 3;
    const int bm = blockIdx.y * 128, bn = blockIdx.x * 128;

    const int arow = tid >> 1, ac0 = (tid & 1) * 16;
    const int brow = tid >> 3, bc0 = (tid & 7) * 16;
    const unsigned smbase = (unsigned)__cvta_generic_to_shared(gsm);

    float acc[4][4][4];
#pragma unroll
    for (int i = 0; i < 4; i++)
#pragma unroll
        for (int j = 0; j < 4; j++)
#pragma unroll
            for (int l = 0; l < 4; l++) acc[i][j][l] = 0.f;

    const int niter = K / BK;
    auto issue = [&](int it) {
        int s = it & 3;
        unsigned da = smbase + (s * STG_TOT + arow * 40 + ac0) * 2;
        const __half* pa = A + (size_t)(bm + arow) * K + it * BK + ac0;
        cpa16(da, pa); cpa16(da + 16, pa + 8);
        unsigned db = smbase + (s * STG_TOT + STG_A + brow * 136 + bc0) * 2;
        const __half* pb = B + (size_t)(it * BK + brow) * N + bn + bc0;
        cpa16(db, pb); cpa16(db + 16, pb + 8);
        cpa_commit();
    };
    issue(0);
    if (niter > 1) issue(1);
    if (niter > 2) issue(2);

    const unsigned aLane = ((lane & 15) * 40 + (lane >> 4) * 8) * 2 + (unsigned)(mw * 64 * 40 * 2);
    const unsigned bLane = (((lane & 7) + ((lane >> 3) & 1) * 8) * 136 + (lane >> 4) * 8) * 2
                           + (unsigned)(nw * 32 * 2);

    for (int it = 0; it < niter; it++) {
        if (it + 2 < niter)      cpa_wait<2>();
        else if (it + 1 < niter) cpa_wait<1>();
        else                     cpa_wait<0>();
        __syncthreads();
        if (it + 3 < niter) issue(it + 3);
        int s = it & 3;
        unsigned aBase = smbase + s * STG_TOT * 2 + aLane;
        unsigned bBase = smbase + (s * STG_TOT + STG_A) * 2 + bLane;
#pragma unroll
        for (int ks = 0; ks < 2; ks++) {
            unsigned a[4][4], b[2][4];
#pragma unroll
            for (int mf = 0; mf < 4; mf++) ldsm_x4(a[mf], aBase + mf * (16 * 40 * 2) + ks * 32);
#pragma unroll
            for (int np = 0; np < 2; np++) ldsm_x4_t(b[np], bBase + np * 32 + ks * (16 * 136 * 2));
#pragma unroll
            for (int mf = 0; mf < 4; mf++)
#pragma unroll
                for (int nf = 0; nf < 4; nf++)
                    mma16816(acc[mf][nf], a[mf], b[nf >> 1][(nf & 1) * 2],
                             b[nf >> 1][(nf & 1) * 2 + 1]);
        }
    }

    if constexpr (EPI == 2) {
        float* stat = (float*)gsm;
        int orA[4], orB[4];
        __syncthreads();
#pragma unroll
        for (int mf = 0; mf < 4; mf++) {
            int lr = mw * 64 + mf * 16 + (lane >> 2);
            orA[mf] = nat_row(bm + lr);
            orB[mf] = nat_row(bm + lr + 8);
            float s0 = 0.f, q0 = 0.f, s1 = 0.f, q1 = 0.f;
#pragma unroll
            for (int nf = 0; nf < 4; nf++) {
                int c = nw * 32 + nf * 8 + (lane & 3) * 2;
                float bv0 = bias[c], bv1 = bias[c + 1];
                float v00 = acc[mf][nf][0] + bv0 + res[(size_t)orA[mf] * DIM + c];
                float v01 = acc[mf][nf][1] + bv1 + res[(size_t)orA[mf] * DIM + c + 1];
                float v10 = acc[mf][nf][2] + bv0 + res[(size_t)orB[mf] * DIM + c];
                float v11 = acc[mf][nf][3] + bv1 + res[(size_t)orB[mf] * DIM + c + 1];
                acc[mf][nf][0] = v00; acc[mf][nf][1] = v01;
                acc[mf][nf][2] = v10; acc[mf][nf][3] = v11;
                s0 += v00 + v01; q0 += v00 * v00 + v01 * v01;
                s1 += v10 + v11; q1 += v10 * v10 + v11 * v11;
            }
#pragma unroll
            for (int ofs = 1; ofs <= 2; ofs <<= 1) {
                s0 += __shfl_xor_sync(0xffffffffu, s0, ofs);
                q0 += __shfl_xor_sync(0xffffffffu, q0, ofs);
                s1 += __shfl_xor_sync(0xffffffffu, s1, ofs);
                q1 += __shfl_xor_sync(0xffffffffu, q1, ofs);
            }
            if ((lane & 3) == 0) {
                stat[lr * 8 + nw] = s0;          stat[lr * 8 + nw + 4] = q0;
                stat[(lr + 8) * 8 + nw] = s1;    stat[(lr + 8) * 8 + nw + 4] = q1;
            }
        }
        __syncthreads();
#pragma unroll
        for (int mf = 0; mf < 4; mf++) {
            int lr = mw * 64 + mf * 16 + (lane >> 2);
            float s0 = stat[lr * 8] + stat[lr * 8 + 1] + stat[lr * 8 + 2] + stat[lr * 8 + 3];
            float q0 = stat[lr * 8 + 4] + stat[lr * 8 + 5] + stat[lr * 8 + 6] + stat[lr * 8 + 7];
            float s1 = stat[(lr + 8) * 8]     + stat[(lr + 8) * 8 + 1]
                     + stat[(lr + 8) * 8 + 2] + stat[(lr + 8) * 8 + 3];
            float q1 = stat[(lr + 8) * 8 + 4] + stat[(lr + 8) * 8 + 5]
                     + stat[(lr + 8) * 8 + 6] + stat[(lr + 8) * 8 + 7];
            float m0 = s0 * (1.f / 128.f);
            float i0 = rsqrtf(q0 * (1.f / 128.f) - m0 * m0 + 1e-5f);
            float m1 = s1 * (1.f / 128.f);
            float i1 = rsqrtf(q1 * (1.f / 128.f) - m1 * m1 + 1e-5f);
#pragma unroll
            for (int nf = 0; nf < 4; nf++) {
                int c = nw * 32 + nf * 8 + (lane & 3) * 2;
                float g0 = g2[c], g1 = g2[c + 1], bb0 = b2[c], bb1 = b2[c + 1];
                float v00 = acc[mf][nf][0], v01 = acc[mf][nf][1];
                float v10 = acc[mf][nf][2], v11 = acc[mf][nf][3];
                *(float2*)((float*)C + (size_t)orA[mf] * DIM + c) = make_float2(v00, v01);
                *(float2*)((float*)C + (size_t)orB[mf] * DIM + c) = make_float2(v10, v11);
                *(__half2*)(C2 + (size_t)orA[mf] * DIM + c) =
                    __floats2half2_rn((v00 - m0) * i0 * g0 + bb0, (v01 - m0) * i0 * g1 + bb1);
                *(__half2*)(C2 + (size_t)orB[mf] * DIM + c) =
                    __floats2half2_rn((v10 - m1) * i1 * g0 + bb0, (v11 - m1) * i1 * g1 + bb1);
            }
        }
    } else {
#pragma unroll
        for (int mf = 0; mf < 4; mf++) {
            int r0 = bm + mw * 64 + mf * 16 + (lane >> 2);
            int r1 = r0 + 8;
#pragma unroll
            for (int nf = 0; nf < 4; nf++) {
                int c = bn + nw * 32 + nf * 8 + (lane & 3) * 2;
                float bv0 = bias[c], bv1 = bias[c + 1];
                float v00 = acc[mf][nf][0] + bv0, v01 = acc[mf][nf][1] + bv1;
                float v10 = acc[mf][nf][2] + bv0, v11 = acc[mf][nf][3] + bv1;
                if (EPI == 1) {
                    v00 = 0.5f * v00 * (1.f + erff(v00 * 0.7071067811865475f));
                    v01 = 0.5f * v01 * (1.f + erff(v01 * 0.7071067811865475f));
                    v10 = 0.5f * v10 * (1.f + erff(v10 * 0.7071067811865475f));
                    v11 = 0.5f * v11 * (1.f + erff(v11 * 0.7071067811865475f));
                }
                if (EPI == 3) {
                    v00 += res[(size_t)r0 * DIM + c];    v01 += res[(size_t)r0 * DIM + c + 1];
                    v10 += res[(size_t)r1 * DIM + c];    v11 += res[(size_t)r1 * DIM + c + 1];
                }
                if constexpr (sizeof(CT) == 2) {
                    *(__half2*)((__half*)C + (size_t)r0 * N + c) = __floats2half2_rn(v00, v01);
                    *(__half2*)((__half*)C + (size_t)r1 * N + c) = __floats2half2_rn(v10, v11);
                } else {
                    *(float2*)((float*)C + (size_t)r0 * N + c) = make_float2(v00, v01);
                    *(float2*)((float*)C + (size_t)r1 * N + c) = make_float2(v10, v11);
                }
            }
        }
    }
}

// ===== FA windowed attention: PAIRED query tiles (K/V ldmatrix loaded once
// per chunk for BOTH of a warp's tiles — halves smem/L1 traffic), exp2 softmax.
#define ATTN_SMEM (3 * PADN * 40 * 2)

__global__ void __launch_bounds__(352, 2) attn_kernel(
        const __half* __restrict__ qkv, const __half* __restrict__ tab,
        __half* __restrict__ attout) {
    extern __shared__ __half asm_[];
    __half* sQ = asm_;
    __half* sK = asm_ + PADN * 40;
    __half* sV = asm_ + 2 * PADN * 40;

    const int w = blockIdx.x >> 2, h = blockIdx.x & 3;
    const int tid = threadIdx.x, lane = tid & 31, warp = tid >> 5;

    for (int idx = tid; idx < PADN * 4; idx += 352) {
        int t = idx >> 2, c = (idx & 3) * 8;
        uint4 zq = {0,0,0,0}, zk = zq, zv = zq;
        if (t < NTOK) {
            const __half* base = qkv + (size_t)(w * NTOK + t) * (3 * DIM) + h * HD + c;
            zq = *(const uint4*)base;
            zk = *(const uint4*)(base + DIM);
            zv = *(const uint4*)(base + 2 * DIM);
        }
        *(uint4*)&sQ[t * 40 + c] = zq;
        *(uint4*)&sK[t * 40 + c] = zk;
        *(uint4*)&sV[t * 40 + c] = zv;
    }
    __syncthreads();

    const int wi = w & 127;
    const int wt = (((wi >> 6) & 1) << 2) | ((((wi >> 3) & 7) == 7) ? 2 : 0) | (((wi & 7) == 7) ? 1 : 0);
    const __half* tb = tab + (size_t)(wt * NH + h) * PADN * PADN;
    const unsigned smbA = (unsigned)__cvta_generic_to_shared(asm_);
    const unsigned kvRow = (unsigned)((lane & 7) + ((lane >> 4) & 1) * 8);
    const unsigned kvCol = (unsigned)(((lane >> 3) & 1) * 8);
    const unsigned vRow  = (unsigned)((lane & 7) + ((lane >> 3) & 1) * 8);
    const unsigned vCol  = (unsigned)((lane >> 4) * 8);
    const int jl = (lane & 3) * 2;

    // this warp's two query tiles: warp and warp+11 (22 tiles total)
    const int m0t[2] = { warp * 16, (warp + 11) * 16 };
    unsigned aq[2][2][4];
    int rA[2];
    const __half* trA[2]; const __half* trB[2];
#pragma unroll
    for (int t = 0; t < 2; t++) {
        unsigned aAddr = smbA + ((m0t[t] + (lane & 15)) * 40 + (lane >> 4) * 8) * 2;
        ldsm_x4(aq[t][0], aAddr);
        ldsm_x4(aq[t][1], aAddr + 32);
        rA[t] = m0t[t] + (lane >> 2);
        trA[t] = tb + (size_t)rA[t] * PADN;
        trB[t] = trA[t] + (size_t)8 * PADN;
    }

    float o[2][4][4];
#pragma unroll
    for (int t = 0; t < 2; t++)
#pragma unroll
        for (int i = 0; i < 4; i++)
#pragma unroll
            for (int j = 0; j < 4; j++) o[t][i][j] = 0.f;
    float lsum[2][2] = {{0.f, 0.f}, {0.f, 0.f}};

    for (int n0 = 0; n0 < PADN; n0 += 16) {
        unsigned kf0[4], kf1[4];
        unsigned kAddr = smbA + (PADN * 40 + (n0 + kvRow) * 40 + kvCol) * 2;
        ldsm_x4(kf0, kAddr);
        ldsm_x4(kf1, kAddr + 32);

        unsigned pa[2][4];
#pragma unroll
        for (int t = 0; t < 2; t++) {
            float s[2][4] = {{0,0,0,0},{0,0,0,0}};
            mma16816(s[0], aq[t][0], kf0[0], kf0[1]);
            mma16816(s[0], aq[t][1], kf1[0], kf1[1]);
            mma16816(s[1], aq[t][0], kf0[2], kf0[3]);
            mma16816(s[1], aq[t][1], kf1[2], kf1[3]);

            int jc = n0 + jl;
            float2 b00 = __half22float2(*(const __half2*)(trA[t] + jc));
            float2 b01 = __half22float2(*(const __half2*)(trA[t] + jc + 8));
            float2 b10 = __half22float2(*(const __half2*)(trB[t] + jc));
            float2 b11 = __half22float2(*(const __half2*)(trB[t] + jc + 8));
            s[0][0] = exp2f(fmaf(s[0][0], QK_SCALE_LOG2, b00.x));
            s[0][1] = exp2f(fmaf(s[0][1], QK_SCALE_LOG2, b00.y));
            s[0][2] = exp2f(fmaf(s[0][2], QK_SCALE_LOG2, b10.x));
            s[0][3] = exp2f(fmaf(s[0][3], QK_SCALE_LOG2, b10.y));
            s[1][0] = exp2f(fmaf(s[1][0], QK_SCALE_LOG2, b01.x));
            s[1][1] = exp2f(fmaf(s[1][1], QK_SCALE_LOG2, b01.y));
            s[1][2] = exp2f(fmaf(s[1][2], QK_SCALE_LOG2, b11.x));
            s[1][3] = exp2f(fmaf(s[1][3], QK_SCALE_LOG2, b11.y));
            lsum[t][0] += s[0][0] + s[0][1] + s[1][0] + s[1][1];
            lsum[t][1] += s[0][2] + s[0][3] + s[1][2] + s[1][3];

            __half2 p0 = __floats2half2_rn(s[0][0], s[0][1]);
            __half2 p1 = __floats2half2_rn(s[0][2], s[0][3]);
            __half2 p2 = __floats2half2_rn(s[1][0], s[1][1]);
            __half2 p3 = __floats2half2_rn(s[1][2], s[1][3]);
            pa[t][0] = *(unsigned*)&p0; pa[t][1] = *(unsigned*)&p1;
            pa[t][2] = *(unsigned*)&p2; pa[t][3] = *(unsigned*)&p3;
        }

        unsigned vf0[4], vf1[4];
        unsigned vAddr = smbA + (2 * PADN * 40 + (n0 + vRow) * 40 + vCol) * 2;
        ldsm_x4_t(vf0, vAddr);
        ldsm_x4_t(vf1, vAddr + 32);
#pragma unroll
        for (int t = 0; t < 2; t++) {
            mma16816(o[t][0], pa[t], vf0[0], vf0[1]);
            mma16816(o[t][1], pa[t], vf0[2], vf0[3]);
            mma16816(o[t][2], pa[t], vf1[0], vf1[1]);
            mma16816(o[t][3], pa[t], vf1[2], vf1[3]);
        }
    }

#pragma unroll
    for (int t = 0; t < 2; t++) {
#pragma unroll
        for (int ofs = 1; ofs <= 2; ofs <<= 1) {
            lsum[t][0] += __shfl_xor_sync(0xffffffffu, lsum[t][0], ofs);
            lsum[t][1] += __shfl_xor_sync(0xffffffffu, lsum[t][1], ofs);
        }
        float inv0 = 1.f / lsum[t][0], inv1 = 1.f / lsum[t][1];
        int r0g = rA[t], r1g = rA[t] + 8;
        int cbase = h * HD + jl;
        if (r0g < NTOK) {
            __half* dst = attout + (size_t)(w * NTOK + r0g) * DIM + cbase;
#pragma unroll
            for (int nf = 0; nf < 4; nf++)
                *(__half2*)(dst + nf * 8) = __floats2half2_rn(o[t][nf][0] * inv0, o[t][nf][1] * inv0);
        }
        if (r1g < NTOK) {
            __half* dst = attout + (size_t)(w * NTOK + r1g) * DIM + cbase;
#pragma unroll
            for (int nf = 0; nf < 4; nf++)
                *(__half2*)(dst + nf * 8) = __floats2half2_rn(o[t][nf][2] * inv1, o[t][nf][3] * inv1);
        }
    }
}

// -------- launch --------
extern "C" void kernel_launch(void* const* d_in, const int* in_sizes, int n_in,
                              void* d_out, int out_size) {
    const float* x     = (const float*)d_in[0];
    const float* n1g   = (const float*)d_in[1];
    const float* n1b   = (const float*)d_in[2];
    const float* qkvw  = (const float*)d_in[3];
    const float* qkvb  = (const float*)d_in[4];
    const float* rel   = (const float*)d_in[5];
    const float* projw = (const float*)d_in[6];
    const float* projb = (const float*)d_in[7];
    const float* n2g   = (const float*)d_in[8];
    const float* n2b   = (const float*)d_in[9];
    const float* fc1w  = (const float*)d_in[10];
    const float* fc1b  = (const float*)d_in[11];
    const float* fc2w  = (const float*)d_in[12];
    const float* fc2b  = (const float*)d_in[13];
    float* out = (float*)d_out;

    __half *xw, *qkvp, *att, *xn2, *hbuf, *wh, *btab;
    float *x1;
    cudaGetSymbolAddress((void**)&xw,   g_xw);
    cudaGetSymbolAddress((void**)&qkvp, g_qkv);
    cudaGetSymbolAddress((void**)&att,  g_att);
    cudaGetSymbolAddress((void**)&x1,   g_x1);
    cudaGetSymbolAddress((void**)&xn2,  g_xn2);
    cudaGetSymbolAddress((void**)&hbuf, g_h);
    cudaGetSymbolAddress((void**)&wh,   g_wh);
    cudaGetSymbolAddress((void**)&btab, g_btab);

    cudaFuncSetAttribute(attn_kernel, cudaFuncAttributeMaxDynamicSharedMemorySize, ATTN_SMEM);
    cudaFuncSetAttribute(mma_gemm<0, __half>, cudaFuncAttributeMaxDynamicSharedMemorySize, GEMM_SMEM);
    cudaFuncSetAttribute(mma_gemm<1, __half>, cudaFuncAttributeMaxDynamicSharedMemorySize, GEMM_SMEM);
    cudaFuncSetAttribute(mma_gemm<2, float>,  cudaFuncAttributeMaxDynamicSharedMemorySize, GEMM_SMEM);
    cudaFuncSetAttribute(mma_gemm<3, float>,  cudaFuncAttributeMaxDynamicSharedMemorySize, GEMM_SMEM);

    // merged prologue (weights->fp16 + exp2-scaled bias/mask table)
    prologue_kernel<<<(NBTAB + 255) / 256, 256>>>(qkvw, projw, fc1w, fc2w, wh, rel, btab);
    // 1) LN1 + shift + window partition
    ln_kernel<<<NROWS / 16, 512>>>(x, n1g, n1b, xw, 1);
    // 2) QKV GEMM
    mma_gemm<0, __half><<<dim3(3, NROWS / 128), 256, GEMM_SMEM>>>(
        xw, wh, qkvb, nullptr, qkvp, nullptr, nullptr, nullptr, NROWS, 384, 128);
    // 3) attention
    attn_kernel<<<NWIN * NH, 352, ATTN_SMEM>>>(qkvp, btab, att);
    // 4) proj + window-reverse + residual + fused LN2
    mma_gemm<2, float><<<dim3(1, NROWS / 128), 256, GEMM_SMEM>>>(
        att, wh + 49152, projb, x, x1, n2g, n2b, xn2, NROWS, 128, 128);
    // 5) fc1 + GELU
    mma_gemm<1, __half><<<dim3(4, NROWS / 128), 256, GEMM_SMEM>>>(
        xn2, wh + 65536, fc1b, nullptr, hbuf, nullptr, nullptr, nullptr, NROWS, 512, 128);
    // 6) fc2 + residual -> out
    mma_gemm<3, float><<<dim3(1, NROWS / 128), 256, GEMM_SMEM>>>(
        hbuf, wh + 131072, fc2b, x1, out, nullptr, nullptr, nullptr, NROWS, 128, 512);
}

// round 16
// speedup vs baseline: 1.0873x; 1.0873x over previous
#include <cuda_runtime.h>
#include <cuda_fp16.h>
#include <math.h>

#define DIM   128
#define NH    4
#define HD    32
#define WS    7
#define SS    3
#define ZP    14
#define HP    56
#define WP    56
#define NTOK  343
#define PADN  352
#define NWIN  256
#define NROWS (NWIN * NTOK)   // 87808
#define NMLP  512
// QK scale folded with 1/ln2 for exp2-based softmax: (1/sqrt(32)) * (1/ln 2)
#define QK_SCALE_LOG2 0.25503164402847864f
#define INV_LN2 1.4426950408889634f

// -------- scratch (static device globals) --------
__device__ __half g_xw [NROWS * DIM];
__device__ __half g_qkv[NROWS * 3 * DIM];
__device__ __half g_att[NROWS * DIM];
__device__ float  g_x1 [NROWS * DIM];
__device__ __half g_xn2[NROWS * DIM];
__device__ __half g_h  [NROWS * NMLP];
__device__ __half g_wh [196608];                       // fp16 weights [K][N]: qkv|proj|fc1|fc2
__device__ __half g_btab[8 * NH * PADN * PADN];        // (bias+mask)/ln2 table (7.9MB)

__device__ __forceinline__ int nat_row(int r) {
    int w = r / NTOK, t = r - w * NTOK;
    int b = w >> 7, wi = w & 127;
    int wz = wi >> 6, wy = (wi >> 3) & 7, wx = wi & 7;
    int lz = t / 49, rem = t - lz * 49, ly = rem / 7, lx = rem - ly * 7;
    int z = wz * WS + lz + SS; if (z >= ZP) z -= ZP;
    int y = wy * WS + ly + SS; if (y >= HP) y -= HP;
    int x = wx * WS + lx + SS; if (x >= WP) x -= WP;
    return ((b * ZP + z) * HP + y) * WP + x;
}

// -------- merged prologue: weight convert + bias/mask table (one launch) --------
#define NBTAB (8 * NH * PADN * PADN)
__global__ void prologue_kernel(const float* __restrict__ qkvw, const float* __restrict__ projw,
                                const float* __restrict__ fc1w, const float* __restrict__ fc2w,
                                __half* __restrict__ o,
                                const float* __restrict__ rel, __half* __restrict__ tab) {
    int idx = blockIdx.x * 256 + threadIdx.x;
    if (idx < 196608) {
        float v;
        if (idx < 49152) v = qkvw[idx];
        else if (idx < 65536) v = projw[idx - 49152];
        else if (idx < 131072) v = fc1w[idx - 65536];
        else v = fc2w[idx - 131072];
        o[idx] = __float2half(v);
    }
    if (idx >= NBTAB) return;
    int j = idx % PADN, t1 = idx / PADN;
    int i = t1 % PADN, t2 = t1 / PADN;
    int h = t2 & 3, wt = t2 >> 2;
    float val;
    if (i >= NTOK || j >= NTOK) val = -30000.f;
    else {
        int iz = i / 49, ir = i - iz * 49, iy = ir / 7, ix = ir - iy * 7;
        int jz = j / 49, jr = j - jz * 49, jy = jr / 7, jx = jr - jy * 7;
        int ridx = (iz - jz + 6) * 169 + (iy - jy + 6) * 13 + (ix - jx + 6);
        int ri = ((wt & 4) ? ((iz < 4) ? 1 : 2) : 0) * 9
               + ((wt & 2) ? ((iy < 4) ? 1 : 2) : 0) * 3
               + ((wt & 1) ? ((ix < 4) ? 1 : 2) : 0);
        int rj = ((wt & 4) ? ((jz < 4) ? 1 : 2) : 0) * 9
               + ((wt & 2) ? ((jy < 4) ? 1 : 2) : 0) * 3
               + ((wt & 1) ? ((jx < 4) ? 1 : 2) : 0);
        val = (rel[ridx * NH + h] + ((ri == rj) ? 0.f : -100.f)) * INV_LN2;
    }
    tab[idx] = __float2half(val);
}

// -------- LayerNorm (LN1): one warp per token, gather + fp16 out, 512 thr --------
__global__ void ln_kernel(const float* __restrict__ src, const float* __restrict__ g,
                          const float* __restrict__ b, __half* __restrict__ dst, int gather) {
    int token = blockIdx.x * 16 + (threadIdx.x >> 5);
    int lane  = threadIdx.x & 31;
    int srow  = gather ? nat_row(token) : token;
    float4 v = ((const float4*)(src + (size_t)srow * DIM))[lane];
    float s  = v.x + v.y + v.z + v.w;
    float ss = v.x * v.x + v.y * v.y + v.z * v.z + v.w * v.w;
#pragma unroll
    for (int o = 16; o; o >>= 1) {
        s  += __shfl_xor_sync(0xffffffffu, s,  o);
        ss += __shfl_xor_sync(0xffffffffu, ss, o);
    }
    float mean = s * (1.f / 128.f);
    float inv  = rsqrtf(ss * (1.f / 128.f) - mean * mean + 1e-5f);
    float4 gg = ((const float4*)g)[lane];
    float4 bb = ((const float4*)b)[lane];
    __half2 h01 = __floats2half2_rn((v.x - mean) * inv * gg.x + bb.x,
                                    (v.y - mean) * inv * gg.y + bb.y);
    __half2 h23 = __floats2half2_rn((v.z - mean) * inv * gg.z + bb.z,
                                    (v.w - mean) * inv * gg.w + bb.w);
    __half2* d = (__half2*)(dst + (size_t)token * DIM);
    d[lane * 2] = h01; d[lane * 2 + 1] = h23;
}

// ================= MMA helpers =================
__device__ __forceinline__ void ldsm_x4(unsigned (&r)[4], unsigned addr) {
    asm volatile("ldmatrix.sync.aligned.m8n8.x4.shared.b16 {%0,%1,%2,%3}, [%4];"
                 : "=r"(r[0]), "=r"(r[1]), "=r"(r[2]), "=r"(r[3]) : "r"(addr));
}
__device__ __forceinline__ void ldsm_x4_t(unsigned (&r)[4], unsigned addr) {
    asm volatile("ldmatrix.sync.aligned.m8n8.x4.trans.shared.b16 {%0,%1,%2,%3}, [%4];"
                 : "=r"(r[0]), "=r"(r[1]), "=r"(r[2]), "=r"(r[3]) : "r"(addr));
}
__device__ __forceinline__ void mma16816(float (&c)[4], const unsigned (&a)[4],
                                         unsigned b0, unsigned b1) {
    asm volatile("mma.sync.aligned.m16n8k16.row.col.f32.f16.f16.f32 "
                 "{%0,%1,%2,%3},{%4,%5,%6,%7},{%8,%9},{%0,%1,%2,%3};"
                 : "+f"(c[0]), "+f"(c[1]), "+f"(c[2]), "+f"(c[3])
                 : "r"(a[0]), "r"(a[1]), "r"(a[2]), "r"(a[3]), "r"(b0), "r"(b1));
}
__device__ __forceinline__ void cpa16(unsigned dst, const void* src) {
    asm volatile("cp.async.cg.shared.global [%0], [%1], 16;" :: "r"(dst), "l"(src));
}
__device__ __forceinline__ void cpa_commit() { asm volatile("cp.async.commit_group;"); }
template <int N> __device__ __forceinline__ void cpa_wait() {
    asm volatile("cp.async.wait_group %0;" :: "n"(N));
}

// ================= tensor-core GEMM, cp.async 4-stage, 1 sync/iter (round-10) ====
#define BK 32
#define STG_A (128 * 40)            // halfs
#define STG_B (BK * 136)
#define STG_TOT (STG_A + STG_B)
#define GEMM_SMEM (4 * STG_TOT * 2) // 75,776 bytes

template <int EPI, typename CT>
__global__ void __launch_bounds__(256, 2) mma_gemm(
        const __half* __restrict__ A, const __half* __restrict__ B,
        const float* __restrict__ bias, const float* __restrict__ res,
        CT* __restrict__ C, const float* __restrict__ g2,
        const float* __restrict__ b2, __half* __restrict__ C2,
        int M, int N, int K) {
    extern __shared__ __half gsm[];
    const int tid  = threadIdx.x;
    const int lane = tid & 31, warp = tid >> 5;
    const int mw = warp >> 2, nw = warp & 3;
    const int bm = blockIdx.y * 128, bn = blockIdx.x * 128;

    const int arow = tid >> 1, ac0 = (tid & 1) * 16;
    const int brow = tid >> 3, bc0 = (tid & 7) * 16;
    const unsigned smbase = (unsigned)__cvta_generic_to_shared(gsm);

    float acc[4][4][4];
#pragma unroll
    for (int i = 0; i < 4; i++)
#pragma unroll
        for (int j = 0; j < 4; j++)
#pragma unroll
            for (int l = 0; l < 4; l++) acc[i][j][l] = 0.f;

    const int niter = K / BK;
    auto issue = [&](int it) {
        int s = it & 3;
        unsigned da = smbase + (s * STG_TOT + arow * 40 + ac0) * 2;
        const __half* pa = A + (size_t)(bm + arow) * K + it * BK + ac0;
        cpa16(da, pa); cpa16(da + 16, pa + 8);
        unsigned db = smbase + (s * STG_TOT + STG_A + brow * 136 + bc0) * 2;
        const __half* pb = B + (size_t)(it * BK + brow) * N + bn + bc0;
        cpa16(db, pb); cpa16(db + 16, pb + 8);
        cpa_commit();
    };
    issue(0);
    if (niter > 1) issue(1);
    if (niter > 2) issue(2);

    const unsigned aLane = ((lane & 15) * 40 + (lane >> 4) * 8) * 2 + (unsigned)(mw * 64 * 40 * 2);
    const unsigned bLane = (((lane & 7) + ((lane >> 3) & 1) * 8) * 136 + (lane >> 4) * 8) * 2
                           + (unsigned)(nw * 32 * 2);

    for (int it = 0; it < niter; it++) {
        if (it + 2 < niter)      cpa_wait<2>();
        else if (it + 1 < niter) cpa_wait<1>();
        else                     cpa_wait<0>();
        __syncthreads();
        if (it + 3 < niter) issue(it + 3);
        int s = it & 3;
        unsigned aBase = smbase + s * STG_TOT * 2 + aLane;
        unsigned bBase = smbase + (s * STG_TOT + STG_A) * 2 + bLane;
#pragma unroll
        for (int ks = 0; ks < 2; ks++) {
            unsigned a[4][4], b[2][4];
#pragma unroll
            for (int mf = 0; mf < 4; mf++) ldsm_x4(a[mf], aBase + mf * (16 * 40 * 2) + ks * 32);
#pragma unroll
            for (int np = 0; np < 2; np++) ldsm_x4_t(b[np], bBase + np * 32 + ks * (16 * 136 * 2));
#pragma unroll
            for (int mf = 0; mf < 4; mf++)
#pragma unroll
                for (int nf = 0; nf < 4; nf++)
                    mma16816(acc[mf][nf], a[mf], b[nf >> 1][(nf & 1) * 2],
                             b[nf >> 1][(nf & 1) * 2 + 1]);
        }
    }

    if constexpr (EPI == 2) {
        float* stat = (float*)gsm;
        int orA[4], orB[4];
        __syncthreads();
#pragma unroll
        for (int mf = 0; mf < 4; mf++) {
            int lr = mw * 64 + mf * 16 + (lane >> 2);
            orA[mf] = nat_row(bm + lr);
            orB[mf] = nat_row(bm + lr + 8);
            float s0 = 0.f, q0 = 0.f, s1 = 0.f, q1 = 0.f;
#pragma unroll
            for (int nf = 0; nf < 4; nf++) {
                int c = nw * 32 + nf * 8 + (lane & 3) * 2;
                float bv0 = bias[c], bv1 = bias[c + 1];
                float v00 = acc[mf][nf][0] + bv0 + res[(size_t)orA[mf] * DIM + c];
                float v01 = acc[mf][nf][1] + bv1 + res[(size_t)orA[mf] * DIM + c + 1];
                float v10 = acc[mf][nf][2] + bv0 + res[(size_t)orB[mf] * DIM + c];
                float v11 = acc[mf][nf][3] + bv1 + res[(size_t)orB[mf] * DIM + c + 1];
                acc[mf][nf][0] = v00; acc[mf][nf][1] = v01;
                acc[mf][nf][2] = v10; acc[mf][nf][3] = v11;
                s0 += v00 + v01; q0 += v00 * v00 + v01 * v01;
                s1 += v10 + v11; q1 += v10 * v10 + v11 * v11;
            }
#pragma unroll
            for (int ofs = 1; ofs <= 2; ofs <<= 1) {
                s0 += __shfl_xor_sync(0xffffffffu, s0, ofs);
                q0 += __shfl_xor_sync(0xffffffffu, q0, ofs);
                s1 += __shfl_xor_sync(0xffffffffu, s1, ofs);
                q1 += __shfl_xor_sync(0xffffffffu, q1, ofs);
            }
            if ((lane & 3) == 0) {
                stat[lr * 8 + nw] = s0;          stat[lr * 8 + nw + 4] = q0;
                stat[(lr + 8) * 8 + nw] = s1;    stat[(lr + 8) * 8 + nw + 4] = q1;
            }
        }
        __syncthreads();
#pragma unroll
        for (int mf = 0; mf < 4; mf++) {
            int lr = mw * 64 + mf * 16 + (lane >> 2);
            float s0 = stat[lr * 8] + stat[lr * 8 + 1] + stat[lr * 8 + 2] + stat[lr * 8 + 3];
            float q0 = stat[lr * 8 + 4] + stat[lr * 8 + 5] + stat[lr * 8 + 6] + stat[lr * 8 + 7];
            float s1 = stat[(lr + 8) * 8]     + stat[(lr + 8) * 8 + 1]
                     + stat[(lr + 8) * 8 + 2] + stat[(lr + 8) * 8 + 3];
            float q1 = stat[(lr + 8) * 8 + 4] + stat[(lr + 8) * 8 + 5]
                     + stat[(lr + 8) * 8 + 6] + stat[(lr + 8) * 8 + 7];
            float m0 = s0 * (1.f / 128.f);
            float i0 = rsqrtf(q0 * (1.f / 128.f) - m0 * m0 + 1e-5f);
            float m1 = s1 * (1.f / 128.f);
            float i1 = rsqrtf(q1 * (1.f / 128.f) - m1 * m1 + 1e-5f);
#pragma unroll
            for (int nf = 0; nf < 4; nf++) {
                int c = nw * 32 + nf * 8 + (lane & 3) * 2;
                float g0 = g2[c], g1 = g2[c + 1], bb0 = b2[c], bb1 = b2[c + 1];
                float v00 = acc[mf][nf][0], v01 = acc[mf][nf][1];
                float v10 = acc[mf][nf][2], v11 = acc[mf][nf][3];
                *(float2*)((float*)C + (size_t)orA[mf] * DIM + c) = make_float2(v00, v01);
                *(float2*)((float*)C + (size_t)orB[mf] * DIM + c) = make_float2(v10, v11);
                *(__half2*)(C2 + (size_t)orA[mf] * DIM + c) =
                    __floats2half2_rn((v00 - m0) * i0 * g0 + bb0, (v01 - m0) * i0 * g1 + bb1);
                *(__half2*)(C2 + (size_t)orB[mf] * DIM + c) =
                    __floats2half2_rn((v10 - m1) * i1 * g0 + bb0, (v11 - m1) * i1 * g1 + bb1);
            }
        }
    } else {
#pragma unroll
        for (int mf = 0; mf < 4; mf++) {
            int r0 = bm + mw * 64 + mf * 16 + (lane >> 2);
            int r1 = r0 + 8;
#pragma unroll
            for (int nf = 0; nf < 4; nf++) {
                int c = bn + nw * 32 + nf * 8 + (lane & 3) * 2;
                float bv0 = bias[c], bv1 = bias[c + 1];
                float v00 = acc[mf][nf][0] + bv0, v01 = acc[mf][nf][1] + bv1;
                float v10 = acc[mf][nf][2] + bv0, v11 = acc[mf][nf][3] + bv1;
                if (EPI == 1) {
                    v00 = 0.5f * v00 * (1.f + erff(v00 * 0.7071067811865475f));
                    v01 = 0.5f * v01 * (1.f + erff(v01 * 0.7071067811865475f));
                    v10 = 0.5f * v10 * (1.f + erff(v10 * 0.7071067811865475f));
                    v11 = 0.5f * v11 * (1.f + erff(v11 * 0.7071067811865475f));
                }
                if (EPI == 3) {
                    v00 += res[(size_t)r0 * DIM + c];    v01 += res[(size_t)r0 * DIM + c + 1];
                    v10 += res[(size_t)r1 * DIM + c];    v11 += res[(size_t)r1 * DIM + c + 1];
                }
                if constexpr (sizeof(CT) == 2) {
                    *(__half2*)((__half*)C + (size_t)r0 * N + c) = __floats2half2_rn(v00, v01);
                    *(__half2*)((__half*)C + (size_t)r1 * N + c) = __floats2half2_rn(v10, v11);
                } else {
                    *(float2*)((float*)C + (size_t)r0 * N + c) = make_float2(v00, v01);
                    *(float2*)((float*)C + (size_t)r1 * N + c) = make_float2(v10, v11);
                }
            }
        }
    }
}

// ===== FA windowed attention: PAIRED query tiles at occupancy 1 (no spills;
// K/V ldmatrix loaded once per chunk for BOTH tiles — halves L1 traffic) =====
#define ATTN_SMEM (3 * PADN * 40 * 2)

__global__ void __launch_bounds__(352, 1) attn_kernel(
        const __half* __restrict__ qkv, const __half* __restrict__ tab,
        __half* __restrict__ attout) {
    extern __shared__ __half asm_[];
    __half* sQ = asm_;
    __half* sK = asm_ + PADN * 40;
    __half* sV = asm_ + 2 * PADN * 40;

    const int w = blockIdx.x >> 2, h = blockIdx.x & 3;
    const int tid = threadIdx.x, lane = tid & 31, warp = tid >> 5;

    for (int idx = tid; idx < PADN * 4; idx += 352) {
        int t = idx >> 2, c = (idx & 3) * 8;
        uint4 zq = {0,0,0,0}, zk = zq, zv = zq;
        if (t < NTOK) {
            const __half* base = qkv + (size_t)(w * NTOK + t) * (3 * DIM) + h * HD + c;
            zq = *(const uint4*)base;
            zk = *(const uint4*)(base + DIM);
            zv = *(const uint4*)(base + 2 * DIM);
        }
        *(uint4*)&sQ[t * 40 + c] = zq;
        *(uint4*)&sK[t * 40 + c] = zk;
        *(uint4*)&sV[t * 40 + c] = zv;
    }
    __syncthreads();

    const int wi = w & 127;
    const int wt = (((wi >> 6) & 1) << 2) | ((((wi >> 3) & 7) == 7) ? 2 : 0) | (((wi & 7) == 7) ? 1 : 0);
    const __half* tb = tab + (size_t)(wt * NH + h) * PADN * PADN;
    const unsigned smbA = (unsigned)__cvta_generic_to_shared(asm_);
    const unsigned kvRow = (unsigned)((lane & 7) + ((lane >> 4) & 1) * 8);
    const unsigned kvCol = (unsigned)(((lane >> 3) & 1) * 8);
    const unsigned vRow  = (unsigned)((lane & 7) + ((lane >> 3) & 1) * 8);
    const unsigned vCol  = (unsigned)((lane >> 4) * 8);
    const int jl = (lane & 3) * 2;

    // this warp's two query tiles: warp and warp+11 (22 tiles total)
    const int m0t[2] = { warp * 16, (warp + 11) * 16 };
    unsigned aq[2][2][4];
    int rA[2];
    const __half* trA[2]; const __half* trB[2];
#pragma unroll
    for (int t = 0; t < 2; t++) {
        unsigned aAddr = smbA + ((m0t[t] + (lane & 15)) * 40 + (lane >> 4) * 8) * 2;
        ldsm_x4(aq[t][0], aAddr);
        ldsm_x4(aq[t][1], aAddr + 32);
        rA[t] = m0t[t] + (lane >> 2);
        trA[t] = tb + (size_t)rA[t] * PADN;
        trB[t] = trA[t] + (size_t)8 * PADN;
    }

    float o[2][4][4];
#pragma unroll
    for (int t = 0; t < 2; t++)
#pragma unroll
        for (int i = 0; i < 4; i++)
#pragma unroll
            for (int j = 0; j < 4; j++) o[t][i][j] = 0.f;
    float lsum[2][2] = {{0.f, 0.f}, {0.f, 0.f}};

    for (int n0 = 0; n0 < PADN; n0 += 16) {
        unsigned kf0[4], kf1[4];
        unsigned kAddr = smbA + (PADN * 40 + (n0 + kvRow) * 40 + kvCol) * 2;
        ldsm_x4(kf0, kAddr);
        ldsm_x4(kf1, kAddr + 32);

        unsigned pa[2][4];
#pragma unroll
        for (int t = 0; t < 2; t++) {
            float s[2][4] = {{0,0,0,0},{0,0,0,0}};
            mma16816(s[0], aq[t][0], kf0[0], kf0[1]);
            mma16816(s[0], aq[t][1], kf1[0], kf1[1]);
            mma16816(s[1], aq[t][0], kf0[2], kf0[3]);
            mma16816(s[1], aq[t][1], kf1[2], kf1[3]);

            int jc = n0 + jl;
            float2 b00 = __half22float2(*(const __half2*)(trA[t] + jc));
            float2 b01 = __half22float2(*(const __half2*)(trA[t] + jc + 8));
            float2 b10 = __half22float2(*(const __half2*)(trB[t] + jc));
            float2 b11 = __half22float2(*(const __half2*)(trB[t] + jc + 8));
            s[0][0] = exp2f(fmaf(s[0][0], QK_SCALE_LOG2, b00.x));
            s[0][1] = exp2f(fmaf(s[0][1], QK_SCALE_LOG2, b00.y));
            s[0][2] = exp2f(fmaf(s[0][2], QK_SCALE_LOG2, b10.x));
            s[0][3] = exp2f(fmaf(s[0][3], QK_SCALE_LOG2, b10.y));
            s[1][0] = exp2f(fmaf(s[1][0], QK_SCALE_LOG2, b01.x));
            s[1][1] = exp2f(fmaf(s[1][1], QK_SCALE_LOG2, b01.y));
            s[1][2] = exp2f(fmaf(s[1][2], QK_SCALE_LOG2, b11.x));
            s[1][3] = exp2f(fmaf(s[1][3], QK_SCALE_LOG2, b11.y));
            lsum[t][0] += s[0][0] + s[0][1] + s[1][0] + s[1][1];
            lsum[t][1] += s[0][2] + s[0][3] + s[1][2] + s[1][3];

            __half2 p0 = __floats2half2_rn(s[0][0], s[0][1]);
            __half2 p1 = __floats2half2_rn(s[0][2], s[0][3]);
            __half2 p2 = __floats2half2_rn(s[1][0], s[1][1]);
            __half2 p3 = __floats2half2_rn(s[1][2], s[1][3]);
            pa[t][0] = *(unsigned*)&p0; pa[t][1] = *(unsigned*)&p1;
            pa[t][2] = *(unsigned*)&p2; pa[t][3] = *(unsigned*)&p3;
        }

        unsigned vf0[4], vf1[4];
        unsigned vAddr = smbA + (2 * PADN * 40 + (n0 + vRow) * 40 + vCol) * 2;
        ldsm_x4_t(vf0, vAddr);
        ldsm_x4_t(vf1, vAddr + 32);
#pragma unroll
        for (int t = 0; t < 2; t++) {
            mma16816(o[t][0], pa[t], vf0[0], vf0[1]);
            mma16816(o[t][1], pa[t], vf0[2], vf0[3]);
            mma16816(o[t][2], pa[t], vf1[0], vf1[1]);
            mma16816(o[t][3], pa[t], vf1[2], vf1[3]);
        }
    }

#pragma unroll
    for (int t = 0; t < 2; t++) {
#pragma unroll
        for (int ofs = 1; ofs <= 2; ofs <<= 1) {
            lsum[t][0] += __shfl_xor_sync(0xffffffffu, lsum[t][0], ofs);
            lsum[t][1] += __shfl_xor_sync(0xffffffffu, lsum[t][1], ofs);
        }
        float inv0 = 1.f / lsum[t][0], inv1 = 1.f / lsum[t][1];
        int r0g = rA[t], r1g = rA[t] + 8;
        int cbase = h * HD + jl;
        if (r0g < NTOK) {
            __half* dst = attout + (size_t)(w * NTOK + r0g) * DIM + cbase;
#pragma unroll
            for (int nf = 0; nf < 4; nf++)
                *(__half2*)(dst + nf * 8) = __floats2half2_rn(o[t][nf][0] * inv0, o[t][nf][1] * inv0);
        }
        if (r1g < NTOK) {
            __half* dst = attout + (size_t)(w * NTOK + r1g) * DIM + cbase;
#pragma unroll
            for (int nf = 0; nf < 4; nf++)
                *(__half2*)(dst + nf * 8) = __floats2half2_rn(o[t][nf][2] * inv1, o[t][nf][3] * inv1);
        }
    }
}

// -------- launch --------
extern "C" void kernel_launch(void* const* d_in, const int* in_sizes, int n_in,
                              void* d_out, int out_size) {
    const float* x     = (const float*)d_in[0];
    const float* n1g   = (const float*)d_in[1];
    const float* n1b   = (const float*)d_in[2];
    const float* qkvw  = (const float*)d_in[3];
    const float* qkvb  = (const float*)d_in[4];
    const float* rel   = (const float*)d_in[5];
    const float* projw = (const float*)d_in[6];
    const float* projb = (const float*)d_in[7];
    const float* n2g   = (const float*)d_in[8];
    const float* n2b   = (const float*)d_in[9];
    const float* fc1w  = (const float*)d_in[10];
    const float* fc1b  = (const float*)d_in[11];
    const float* fc2w  = (const float*)d_in[12];
    const float* fc2b  = (const float*)d_in[13];
    float* out = (float*)d_out;

    __half *xw, *qkvp, *att, *xn2, *hbuf, *wh, *btab;
    float *x1;
    cudaGetSymbolAddress((void**)&xw,   g_xw);
    cudaGetSymbolAddress((void**)&qkvp, g_qkv);
    cudaGetSymbolAddress((void**)&att,  g_att);
    cudaGetSymbolAddress((void**)&x1,   g_x1);
    cudaGetSymbolAddress((void**)&xn2,  g_xn2);
    cudaGetSymbolAddress((void**)&hbuf, g_h);
    cudaGetSymbolAddress((void**)&wh,   g_wh);
    cudaGetSymbolAddress((void**)&btab, g_btab);

    cudaFuncSetAttribute(attn_kernel, cudaFuncAttributeMaxDynamicSharedMemorySize, ATTN_SMEM);
    cudaFuncSetAttribute(mma_gemm<0, __half>, cudaFuncAttributeMaxDynamicSharedMemorySize, GEMM_SMEM);
    cudaFuncSetAttribute(mma_gemm<1, __half>, cudaFuncAttributeMaxDynamicSharedMemorySize, GEMM_SMEM);
    cudaFuncSetAttribute(mma_gemm<2, float>,  cudaFuncAttributeMaxDynamicSharedMemorySize, GEMM_SMEM);
    cudaFuncSetAttribute(mma_gemm<3, float>,  cudaFuncAttributeMaxDynamicSharedMemorySize, GEMM_SMEM);

    // merged prologue (weights->fp16 + exp2-scaled bias/mask table)
    prologue_kernel<<<(NBTAB + 255) / 256, 256>>>(qkvw, projw, fc1w, fc2w, wh, rel, btab);
    // 1) LN1 + shift + window partition
    ln_kernel<<<NROWS / 16, 512>>>(x, n1g, n1b, xw, 1);
    // 2) QKV GEMM
    mma_gemm<0, __half><<<dim3(3, NROWS / 128), 256, GEMM_SMEM>>>(
        xw, wh, qkvb, nullptr, qkvp, nullptr, nullptr, nullptr, NROWS, 384, 128);
    // 3) attention
    attn_kernel<<<NWIN * NH, 352, ATTN_SMEM>>>(qkvp, btab, att);
    // 4) proj + window-reverse + residual + fused LN2
    mma_gemm<2, float><<<dim3(1, NROWS / 128), 256, GEMM_SMEM>>>(
        att, wh + 49152, projb, x, x1, n2g, n2b, xn2, NROWS, 128, 128);
    // 5) fc1 + GELU
    mma_gemm<1, __half><<<dim3(4, NROWS / 128), 256, GEMM_SMEM>>>(
        xn2, wh + 65536, fc1b, nullptr, hbuf, nullptr, nullptr, nullptr, NROWS, 512, 128);
    // 6) fc2 + residual -> out
    mma_gemm<3, float><<<dim3(1, NROWS / 128), 256, GEMM_SMEM>>>(
        hbuf, wh + 131072, fc2b, x1, out, nullptr, nullptr, nullptr, NROWS, 128, 512);
}

// round 17
// speedup vs baseline: 1.1041x; 1.0154x over previous
#include <cuda_runtime.h>
#include <cuda_fp16.h>
#include <math.h>

#define DIM   128
#define NH    4
#define HD    32
#define WS    7
#define SS    3
#define ZP    14
#define HP    56
#define WP    56
#define NTOK  343
#define PADN  352
#define NWIN  256
#define NROWS (NWIN * NTOK)   // 87808
#define NMLP  512
// QK scale folded with 1/ln2 for exp2-based softmax: (1/sqrt(32)) * (1/ln 2)
#define QK_SCALE_LOG2 0.25503164402847864f
#define INV_LN2 1.4426950408889634f

// -------- scratch (static device globals) --------
__device__ __half g_xw [NROWS * DIM];
__device__ __half g_qkv[NROWS * 3 * DIM];
__device__ __half g_att[NROWS * DIM];
__device__ float  g_x1 [NROWS * DIM];
__device__ __half g_xn2[NROWS * DIM];
__device__ __half g_h  [NROWS * NMLP];
__device__ __half g_wh [196608];                       // fp16 weights [K][N]: qkv|proj|fc1|fc2
__device__ __half g_btab[8 * NH * PADN * PADN];        // (bias+mask)/ln2 table (7.9MB)

__device__ __forceinline__ int nat_row(int r) {
    int w = r / NTOK, t = r - w * NTOK;
    int b = w >> 7, wi = w & 127;
    int wz = wi >> 6, wy = (wi >> 3) & 7, wx = wi & 7;
    int lz = t / 49, rem = t - lz * 49, ly = rem / 7, lx = rem - ly * 7;
    int z = wz * WS + lz + SS; if (z >= ZP) z -= ZP;
    int y = wy * WS + ly + SS; if (y >= HP) y -= HP;
    int x = wx * WS + lx + SS; if (x >= WP) x -= WP;
    return ((b * ZP + z) * HP + y) * WP + x;
}

// -------- merged prologue: weight convert + bias/mask table (one launch) --------
#define NBTAB (8 * NH * PADN * PADN)
__global__ void prologue_kernel(const float* __restrict__ qkvw, const float* __restrict__ projw,
                                const float* __restrict__ fc1w, const float* __restrict__ fc2w,
                                __half* __restrict__ o,
                                const float* __restrict__ rel, __half* __restrict__ tab) {
    int idx = blockIdx.x * 256 + threadIdx.x;
    if (idx < 196608) {
        float v;
        if (idx < 49152) v = qkvw[idx];
        else if (idx < 65536) v = projw[idx - 49152];
        else if (idx < 131072) v = fc1w[idx - 65536];
        else v = fc2w[idx - 131072];
        o[idx] = __float2half(v);
    }
    if (idx >= NBTAB) return;
    int j = idx % PADN, t1 = idx / PADN;
    int i = t1 % PADN, t2 = t1 / PADN;
    int h = t2 & 3, wt = t2 >> 2;
    float val;
    if (i >= NTOK || j >= NTOK) val = -30000.f;
    else {
        int iz = i / 49, ir = i - iz * 49, iy = ir / 7, ix = ir - iy * 7;
        int jz = j / 49, jr = j - jz * 49, jy = jr / 7, jx = jr - jy * 7;
        int ridx = (iz - jz + 6) * 169 + (iy - jy + 6) * 13 + (ix - jx + 6);
        int ri = ((wt & 4) ? ((iz < 4) ? 1 : 2) : 0) * 9
               + ((wt & 2) ? ((iy < 4) ? 1 : 2) : 0) * 3
               + ((wt & 1) ? ((ix < 4) ? 1 : 2) : 0);
        int rj = ((wt & 4) ? ((jz < 4) ? 1 : 2) : 0) * 9
               + ((wt & 2) ? ((jy < 4) ? 1 : 2) : 0) * 3
               + ((wt & 1) ? ((jx < 4) ? 1 : 2) : 0);
        val = (rel[ridx * NH + h] + ((ri == rj) ? 0.f : -100.f)) * INV_LN2;
    }
    tab[idx] = __float2half(val);
}

// -------- LayerNorm (LN1): one warp per token, gather + fp16 out, 512 thr --------
__global__ void ln_kernel(const float* __restrict__ src, const float* __restrict__ g,
                          const float* __restrict__ b, __half* __restrict__ dst, int gather) {
    int token = blockIdx.x * 16 + (threadIdx.x >> 5);
    int lane  = threadIdx.x & 31;
    int srow  = gather ? nat_row(token) : token;
    float4 v = ((const float4*)(src + (size_t)srow * DIM))[lane];
    float s  = v.x + v.y + v.z + v.w;
    float ss = v.x * v.x + v.y * v.y + v.z * v.z + v.w * v.w;
#pragma unroll
    for (int o = 16; o; o >>= 1) {
        s  += __shfl_xor_sync(0xffffffffu, s,  o);
        ss += __shfl_xor_sync(0xffffffffu, ss, o);
    }
    float mean = s * (1.f / 128.f);
    float inv  = rsqrtf(ss * (1.f / 128.f) - mean * mean + 1e-5f);
    float4 gg = ((const float4*)g)[lane];
    float4 bb = ((const float4*)b)[lane];
    __half2 h01 = __floats2half2_rn((v.x - mean) * inv * gg.x + bb.x,
                                    (v.y - mean) * inv * gg.y + bb.y);
    __half2 h23 = __floats2half2_rn((v.z - mean) * inv * gg.z + bb.z,
                                    (v.w - mean) * inv * gg.w + bb.w);
    __half2* d = (__half2*)(dst + (size_t)token * DIM);
    d[lane * 2] = h01; d[lane * 2 + 1] = h23;
}

// ================= MMA helpers =================
__device__ __forceinline__ void ldsm_x4(unsigned (&r)[4], unsigned addr) {
    asm volatile("ldmatrix.sync.aligned.m8n8.x4.shared.b16 {%0,%1,%2,%3}, [%4];"
                 : "=r"(r[0]), "=r"(r[1]), "=r"(r[2]), "=r"(r[3]) : "r"(addr));
}
__device__ __forceinline__ void ldsm_x4_t(unsigned (&r)[4], unsigned addr) {
    asm volatile("ldmatrix.sync.aligned.m8n8.x4.trans.shared.b16 {%0,%1,%2,%3}, [%4];"
                 : "=r"(r[0]), "=r"(r[1]), "=r"(r[2]), "=r"(r[3]) : "r"(addr));
}
__device__ __forceinline__ void mma16816(float (&c)[4], const unsigned (&a)[4],
                                         unsigned b0, unsigned b1) {
    asm volatile("mma.sync.aligned.m16n8k16.row.col.f32.f16.f16.f32 "
                 "{%0,%1,%2,%3},{%4,%5,%6,%7},{%8,%9},{%0,%1,%2,%3};"
                 : "+f"(c[0]), "+f"(c[1]), "+f"(c[2]), "+f"(c[3])
                 : "r"(a[0]), "r"(a[1]), "r"(a[2]), "r"(a[3]), "r"(b0), "r"(b1));
}
__device__ __forceinline__ void cpa16(unsigned dst, const void* src) {
    asm volatile("cp.async.cg.shared.global [%0], [%1], 16;" :: "r"(dst), "l"(src));
}
__device__ __forceinline__ void cpa_commit() { asm volatile("cp.async.commit_group;"); }
template <int N> __device__ __forceinline__ void cpa_wait() {
    asm volatile("cp.async.wait_group %0;" :: "n"(N));
}

// ================= tensor-core GEMM, cp.async 4-stage, 1 sync/iter (round-10) ====
#define BK 32
#define STG_A (128 * 40)            // halfs
#define STG_B (BK * 136)
#define STG_TOT (STG_A + STG_B)
#define GEMM_SMEM (4 * STG_TOT * 2) // 75,776 bytes

template <int EPI, typename CT>
__global__ void __launch_bounds__(256, 2) mma_gemm(
        const __half* __restrict__ A, const __half* __restrict__ B,
        const float* __restrict__ bias, const float* __restrict__ res,
        CT* __restrict__ C, const float* __restrict__ g2,
        const float* __restrict__ b2, __half* __restrict__ C2,
        int M, int N, int K) {
    extern __shared__ __half gsm[];
    const int tid  = threadIdx.x;
    const int lane = tid & 31, warp = tid >> 5;
    const int mw = warp >> 2, nw = warp & 3;
    const int bm = blockIdx.y * 128, bn = blockIdx.x * 128;

    const int arow = tid >> 1, ac0 = (tid & 1) * 16;
    const int brow = tid >> 3, bc0 = (tid & 7) * 16;
    const unsigned smbase = (unsigned)__cvta_generic_to_shared(gsm);

    float acc[4][4][4];
#pragma unroll
    for (int i = 0; i < 4; i++)
#pragma unroll
        for (int j = 0; j < 4; j++)
#pragma unroll
            for (int l = 0; l < 4; l++) acc[i][j][l] = 0.f;

    const int niter = K / BK;
    auto issue = [&](int it) {
        int s = it & 3;
        unsigned da = smbase + (s * STG_TOT + arow * 40 + ac0) * 2;
        const __half* pa = A + (size_t)(bm + arow) * K + it * BK + ac0;
        cpa16(da, pa); cpa16(da + 16, pa + 8);
        unsigned db = smbase + (s * STG_TOT + STG_A + brow * 136 + bc0) * 2;
        const __half* pb = B + (size_t)(it * BK + brow) * N + bn + bc0;
        cpa16(db, pb); cpa16(db + 16, pb + 8);
        cpa_commit();
    };
    issue(0);
    if (niter > 1) issue(1);
    if (niter > 2) issue(2);

    const unsigned aLane = ((lane & 15) * 40 + (lane >> 4) * 8) * 2 + (unsigned)(mw * 64 * 40 * 2);
    const unsigned bLane = (((lane & 7) + ((lane >> 3) & 1) * 8) * 136 + (lane >> 4) * 8) * 2
                           + (unsigned)(nw * 32 * 2);

    for (int it = 0; it < niter; it++) {
        if (it + 2 < niter)      cpa_wait<2>();
        else if (it + 1 < niter) cpa_wait<1>();
        else                     cpa_wait<0>();
        __syncthreads();
        if (it + 3 < niter) issue(it + 3);
        int s = it & 3;
        unsigned aBase = smbase + s * STG_TOT * 2 + aLane;
        unsigned bBase = smbase + (s * STG_TOT + STG_A) * 2 + bLane;
#pragma unroll
        for (int ks = 0; ks < 2; ks++) {
            unsigned a[4][4], b[2][4];
#pragma unroll
            for (int mf = 0; mf < 4; mf++) ldsm_x4(a[mf], aBase + mf * (16 * 40 * 2) + ks * 32);
#pragma unroll
            for (int np = 0; np < 2; np++) ldsm_x4_t(b[np], bBase + np * 32 + ks * (16 * 136 * 2));
#pragma unroll
            for (int mf = 0; mf < 4; mf++)
#pragma unroll
                for (int nf = 0; nf < 4; nf++)
                    mma16816(acc[mf][nf], a[mf], b[nf >> 1][(nf & 1) * 2],
                             b[nf >> 1][(nf & 1) * 2 + 1]);
        }
    }

    if constexpr (EPI == 2) {
        float* stat = (float*)gsm;
        int orA[4], orB[4];
        __syncthreads();
#pragma unroll
        for (int mf = 0; mf < 4; mf++) {
            int lr = mw * 64 + mf * 16 + (lane >> 2);
            orA[mf] = nat_row(bm + lr);
            orB[mf] = nat_row(bm + lr + 8);
            float s0 = 0.f, q0 = 0.f, s1 = 0.f, q1 = 0.f;
#pragma unroll
            for (int nf = 0; nf < 4; nf++) {
                int c = nw * 32 + nf * 8 + (lane & 3) * 2;
                float bv0 = bias[c], bv1 = bias[c + 1];
                float v00 = acc[mf][nf][0] + bv0 + res[(size_t)orA[mf] * DIM + c];
                float v01 = acc[mf][nf][1] + bv1 + res[(size_t)orA[mf] * DIM + c + 1];
                float v10 = acc[mf][nf][2] + bv0 + res[(size_t)orB[mf] * DIM + c];
                float v11 = acc[mf][nf][3] + bv1 + res[(size_t)orB[mf] * DIM + c + 1];
                acc[mf][nf][0] = v00; acc[mf][nf][1] = v01;
                acc[mf][nf][2] = v10; acc[mf][nf][3] = v11;
                s0 += v00 + v01; q0 += v00 * v00 + v01 * v01;
                s1 += v10 + v11; q1 += v10 * v10 + v11 * v11;
            }
#pragma unroll
            for (int ofs = 1; ofs <= 2; ofs <<= 1) {
                s0 += __shfl_xor_sync(0xffffffffu, s0, ofs);
                q0 += __shfl_xor_sync(0xffffffffu, q0, ofs);
                s1 += __shfl_xor_sync(0xffffffffu, s1, ofs);
                q1 += __shfl_xor_sync(0xffffffffu, q1, ofs);
            }
            if ((lane & 3) == 0) {
                stat[lr * 8 + nw] = s0;          stat[lr * 8 + nw + 4] = q0;
                stat[(lr + 8) * 8 + nw] = s1;    stat[(lr + 8) * 8 + nw + 4] = q1;
            }
        }
        __syncthreads();
#pragma unroll
        for (int mf = 0; mf < 4; mf++) {
            int lr = mw * 64 + mf * 16 + (lane >> 2);
            float s0 = stat[lr * 8] + stat[lr * 8 + 1] + stat[lr * 8 + 2] + stat[lr * 8 + 3];
            float q0 = stat[lr * 8 + 4] + stat[lr * 8 + 5] + stat[lr * 8 + 6] + stat[lr * 8 + 7];
            float s1 = stat[(lr + 8) * 8]     + stat[(lr + 8) * 8 + 1]
                     + stat[(lr + 8) * 8 + 2] + stat[(lr + 8) * 8 + 3];
            float q1 = stat[(lr + 8) * 8 + 4] + stat[(lr + 8) * 8 + 5]
                     + stat[(lr + 8) * 8 + 6] + stat[(lr + 8) * 8 + 7];
            float m0 = s0 * (1.f / 128.f);
            float i0 = rsqrtf(q0 * (1.f / 128.f) - m0 * m0 + 1e-5f);
            float m1 = s1 * (1.f / 128.f);
            float i1 = rsqrtf(q1 * (1.f / 128.f) - m1 * m1 + 1e-5f);
#pragma unroll
            for (int nf = 0; nf < 4; nf++) {
                int c = nw * 32 + nf * 8 + (lane & 3) * 2;
                float g0 = g2[c], g1 = g2[c + 1], bb0 = b2[c], bb1 = b2[c + 1];
                float v00 = acc[mf][nf][0], v01 = acc[mf][nf][1];
                float v10 = acc[mf][nf][2], v11 = acc[mf][nf][3];
                *(float2*)((float*)C + (size_t)orA[mf] * DIM + c) = make_float2(v00, v01);
                *(float2*)((float*)C + (size_t)orB[mf] * DIM + c) = make_float2(v10, v11);
                *(__half2*)(C2 + (size_t)orA[mf] * DIM + c) =
                    __floats2half2_rn((v00 - m0) * i0 * g0 + bb0, (v01 - m0) * i0 * g1 + bb1);
                *(__half2*)(C2 + (size_t)orB[mf] * DIM + c) =
                    __floats2half2_rn((v10 - m1) * i1 * g0 + bb0, (v11 - m1) * i1 * g1 + bb1);
            }
        }
    } else {
#pragma unroll
        for (int mf = 0; mf < 4; mf++) {
            int r0 = bm + mw * 64 + mf * 16 + (lane >> 2);
            int r1 = r0 + 8;
#pragma unroll
            for (int nf = 0; nf < 4; nf++) {
                int c = bn + nw * 32 + nf * 8 + (lane & 3) * 2;
                float bv0 = bias[c], bv1 = bias[c + 1];
                float v00 = acc[mf][nf][0] + bv0, v01 = acc[mf][nf][1] + bv1;
                float v10 = acc[mf][nf][2] + bv0, v11 = acc[mf][nf][3] + bv1;
                if (EPI == 1) {
                    v00 = 0.5f * v00 * (1.f + erff(v00 * 0.7071067811865475f));
                    v01 = 0.5f * v01 * (1.f + erff(v01 * 0.7071067811865475f));
                    v10 = 0.5f * v10 * (1.f + erff(v10 * 0.7071067811865475f));
                    v11 = 0.5f * v11 * (1.f + erff(v11 * 0.7071067811865475f));
                }
                if (EPI == 3) {
                    v00 += res[(size_t)r0 * DIM + c];    v01 += res[(size_t)r0 * DIM + c + 1];
                    v10 += res[(size_t)r1 * DIM + c];    v11 += res[(size_t)r1 * DIM + c + 1];
                }
                if constexpr (sizeof(CT) == 2) {
                    *(__half2*)((__half*)C + (size_t)r0 * N + c) = __floats2half2_rn(v00, v01);
                    *(__half2*)((__half*)C + (size_t)r1 * N + c) = __floats2half2_rn(v10, v11);
                } else {
                    *(float2*)((float*)C + (size_t)r0 * N + c) = make_float2(v00, v01);
                    *(float2*)((float*)C + (size_t)r1 * N + c) = make_float2(v10, v11);
                }
            }
        }
    }
}

// ===== FA windowed attention: paired tiles @occ1 + f16x2 exp2 softmax =====
#define ATTN_SMEM (3 * PADN * 40 * 2)

__global__ void __launch_bounds__(352, 1) attn_kernel(
        const __half* __restrict__ qkv, const __half* __restrict__ tab,
        __half* __restrict__ attout) {
    extern __shared__ __half asm_[];
    __half* sQ = asm_;
    __half* sK = asm_ + PADN * 40;
    __half* sV = asm_ + 2 * PADN * 40;

    const int w = blockIdx.x >> 2, h = blockIdx.x & 3;
    const int tid = threadIdx.x, lane = tid & 31, warp = tid >> 5;

    for (int idx = tid; idx < PADN * 4; idx += 352) {
        int t = idx >> 2, c = (idx & 3) * 8;
        uint4 zq = {0,0,0,0}, zk = zq, zv = zq;
        if (t < NTOK) {
            const __half* base = qkv + (size_t)(w * NTOK + t) * (3 * DIM) + h * HD + c;
            zq = *(const uint4*)base;
            zk = *(const uint4*)(base + DIM);
            zv = *(const uint4*)(base + 2 * DIM);
        }
        *(uint4*)&sQ[t * 40 + c] = zq;
        *(uint4*)&sK[t * 40 + c] = zk;
        *(uint4*)&sV[t * 40 + c] = zv;
    }
    __syncthreads();

    const int wi = w & 127;
    const int wt = (((wi >> 6) & 1) << 2) | ((((wi >> 3) & 7) == 7) ? 2 : 0) | (((wi & 7) == 7) ? 1 : 0);
    const __half* tb = tab + (size_t)(wt * NH + h) * PADN * PADN;
    const unsigned smbA = (unsigned)__cvta_generic_to_shared(asm_);
    const unsigned kvRow = (unsigned)((lane & 7) + ((lane >> 4) & 1) * 8);
    const unsigned kvCol = (unsigned)(((lane >> 3) & 1) * 8);
    const unsigned vRow  = (unsigned)((lane & 7) + ((lane >> 3) & 1) * 8);
    const unsigned vCol  = (unsigned)((lane >> 4) * 8);
    const int jl = (lane & 3) * 2;
    const __half2 C2 = __floats2half2_rn(QK_SCALE_LOG2, QK_SCALE_LOG2);

    // this warp's two query tiles: warp and warp+11 (22 tiles total)
    const int m0t[2] = { warp * 16, (warp + 11) * 16 };
    unsigned aq[2][2][4];
    int rA[2];
    const __half* trA[2]; const __half* trB[2];
#pragma unroll
    for (int t = 0; t < 2; t++) {
        unsigned aAddr = smbA + ((m0t[t] + (lane & 15)) * 40 + (lane >> 4) * 8) * 2;
        ldsm_x4(aq[t][0], aAddr);
        ldsm_x4(aq[t][1], aAddr + 32);
        rA[t] = m0t[t] + (lane >> 2);
        trA[t] = tb + (size_t)rA[t] * PADN;
        trB[t] = trA[t] + (size_t)8 * PADN;
    }

    float o[2][4][4];
#pragma unroll
    for (int t = 0; t < 2; t++)
#pragma unroll
        for (int i = 0; i < 4; i++)
#pragma unroll
            for (int j = 0; j < 4; j++) o[t][i][j] = 0.f;
    float lsum[2][2] = {{0.f, 0.f}, {0.f, 0.f}};

    for (int n0 = 0; n0 < PADN; n0 += 16) {
        unsigned kf0[4], kf1[4];
        unsigned kAddr = smbA + (PADN * 40 + (n0 + kvRow) * 40 + kvCol) * 2;
        ldsm_x4(kf0, kAddr);
        ldsm_x4(kf1, kAddr + 32);

        unsigned pa[2][4];
#pragma unroll
        for (int t = 0; t < 2; t++) {
            float s[2][4] = {{0,0,0,0},{0,0,0,0}};
            mma16816(s[0], aq[t][0], kf0[0], kf0[1]);
            mma16816(s[0], aq[t][1], kf1[0], kf1[1]);
            mma16816(s[1], aq[t][0], kf0[2], kf0[3]);
            mma16816(s[1], aq[t][1], kf1[2], kf1[3]);

            int jc = n0 + jl;
            // pack scores, fp16 fma with (bias+mask)/ln2 table, f16x2 exp2
            __half2 sh0 = __floats2half2_rn(s[0][0], s[0][1]);   // row0, col group 0
            __half2 sh1 = __floats2half2_rn(s[0][2], s[0][3]);   // row1, col group 0
            __half2 sh2 = __floats2half2_rn(s[1][0], s[1][1]);   // row0, col group 1
            __half2 sh3 = __floats2half2_rn(s[1][2], s[1][3]);   // row1, col group 1
            __half2 p0 = h2exp2(__hfma2(sh0, C2, *(const __half2*)(trA[t] + jc)));
            __half2 p1 = h2exp2(__hfma2(sh1, C2, *(const __half2*)(trB[t] + jc)));
            __half2 p2 = h2exp2(__hfma2(sh2, C2, *(const __half2*)(trA[t] + jc + 8)));
            __half2 p3 = h2exp2(__hfma2(sh3, C2, *(const __half2*)(trB[t] + jc + 8)));
            pa[t][0] = *(unsigned*)&p0; pa[t][1] = *(unsigned*)&p1;
            pa[t][2] = *(unsigned*)&p2; pa[t][3] = *(unsigned*)&p3;
            float2 f0 = __half22float2(p0), f1 = __half22float2(p1);
            float2 f2 = __half22float2(p2), f3 = __half22float2(p3);
            lsum[t][0] += f0.x + f0.y + f2.x + f2.y;
            lsum[t][1] += f1.x + f1.y + f3.x + f3.y;
        }

        unsigned vf0[4], vf1[4];
        unsigned vAddr = smbA + (2 * PADN * 40 + (n0 + vRow) * 40 + vCol) * 2;
        ldsm_x4_t(vf0, vAddr);
        ldsm_x4_t(vf1, vAddr + 32);
#pragma unroll
        for (int t = 0; t < 2; t++) {
            mma16816(o[t][0], pa[t], vf0[0], vf0[1]);
            mma16816(o[t][1], pa[t], vf0[2], vf0[3]);
            mma16816(o[t][2], pa[t], vf1[0], vf1[1]);
            mma16816(o[t][3], pa[t], vf1[2], vf1[3]);
        }
    }

#pragma unroll
    for (int t = 0; t < 2; t++) {
#pragma unroll
        for (int ofs = 1; ofs <= 2; ofs <<= 1) {
            lsum[t][0] += __shfl_xor_sync(0xffffffffu, lsum[t][0], ofs);
            lsum[t][1] += __shfl_xor_sync(0xffffffffu, lsum[t][1], ofs);
        }
        float inv0 = 1.f / lsum[t][0], inv1 = 1.f / lsum[t][1];
        int r0g = rA[t], r1g = rA[t] + 8;
        int cbase = h * HD + jl;
        if (r0g < NTOK) {
            __half* dst = attout + (size_t)(w * NTOK + r0g) * DIM + cbase;
#pragma unroll
            for (int nf = 0; nf < 4; nf++)
                *(__half2*)(dst + nf * 8) = __floats2half2_rn(o[t][nf][0] * inv0, o[t][nf][1] * inv0);
        }
        if (r1g < NTOK) {
            __half* dst = attout + (size_t)(w * NTOK + r1g) * DIM + cbase;
#pragma unroll
            for (int nf = 0; nf < 4; nf++)
                *(__half2*)(dst + nf * 8) = __floats2half2_rn(o[t][nf][2] * inv1, o[t][nf][3] * inv1);
        }
    }
}

// -------- launch --------
extern "C" void kernel_launch(void* const* d_in, const int* in_sizes, int n_in,
                              void* d_out, int out_size) {
    const float* x     = (const float*)d_in[0];
    const float* n1g   = (const float*)d_in[1];
    const float* n1b   = (const float*)d_in[2];
    const float* qkvw  = (const float*)d_in[3];
    const float* qkvb  = (const float*)d_in[4];
    const float* rel   = (const float*)d_in[5];
    const float* projw = (const float*)d_in[6];
    const float* projb = (const float*)d_in[7];
    const float* n2g   = (const float*)d_in[8];
    const float* n2b   = (const float*)d_in[9];
    const float* fc1w  = (const float*)d_in[10];
    const float* fc1b  = (const float*)d_in[11];
    const float* fc2w  = (const float*)d_in[12];
    const float* fc2b  = (const float*)d_in[13];
    float* out = (float*)d_out;

    __half *xw, *qkvp, *att, *xn2, *hbuf, *wh, *btab;
    float *x1;
    cudaGetSymbolAddress((void**)&xw,   g_xw);
    cudaGetSymbolAddress((void**)&qkvp, g_qkv);
    cudaGetSymbolAddress((void**)&att,  g_att);
    cudaGetSymbolAddress((void**)&x1,   g_x1);
    cudaGetSymbolAddress((void**)&xn2,  g_xn2);
    cudaGetSymbolAddress((void**)&hbuf, g_h);
    cudaGetSymbolAddress((void**)&wh,   g_wh);
    cudaGetSymbolAddress((void**)&btab, g_btab);

    cudaFuncSetAttribute(attn_kernel, cudaFuncAttributeMaxDynamicSharedMemorySize, ATTN_SMEM);
    cudaFuncSetAttribute(mma_gemm<0, __half>, cudaFuncAttributeMaxDynamicSharedMemorySize, GEMM_SMEM);
    cudaFuncSetAttribute(mma_gemm<1, __half>, cudaFuncAttributeMaxDynamicSharedMemorySize, GEMM_SMEM);
    cudaFuncSetAttribute(mma_gemm<2, float>,  cudaFuncAttributeMaxDynamicSharedMemorySize, GEMM_SMEM);
    cudaFuncSetAttribute(mma_gemm<3, float>,  cudaFuncAttributeMaxDynamicSharedMemorySize, GEMM_SMEM);

    // merged prologue (weights->fp16 + exp2-scaled bias/mask table)
    prologue_kernel<<<(NBTAB + 255) / 256, 256>>>(qkvw, projw, fc1w, fc2w, wh, rel, btab);
    // 1) LN1 + shift + window partition
    ln_kernel<<<NROWS / 16, 512>>>(x, n1g, n1b, xw, 1);
    // 2) QKV GEMM
    mma_gemm<0, __half><<<dim3(3, NROWS / 128), 256, GEMM_SMEM>>>(
        xw, wh, qkvb, nullptr, qkvp, nullptr, nullptr, nullptr, NROWS, 384, 128);
    // 3) attention
    attn_kernel<<<NWIN * NH, 352, ATTN_SMEM>>>(qkvp, btab, att);
    // 4) proj + window-reverse + residual + fused LN2
    mma_gemm<2, float><<<dim3(1, NROWS / 128), 256, GEMM_SMEM>>>(
        att, wh + 49152, projb, x, x1, n2g, n2b, xn2, NROWS, 128, 128);
    // 5) fc1 + GELU
    mma_gemm<1, __half><<<dim3(4, NROWS / 128), 256, GEMM_SMEM>>>(
        xn2, wh + 65536, fc1b, nullptr, hbuf, nullptr, nullptr, nullptr, NROWS, 512, 128);
    // 6) fc2 + residual -> out
    mma_gemm<3, float><<<dim3(1, NROWS / 128), 256, GEMM_SMEM>>>(
        hbuf, wh + 131072, fc2b, x1, out, nullptr, nullptr, nullptr, NROWS, 128, 512);
}